// round 1
// baseline (speedup 1.0000x reference)
#include <cuda_runtime.h>
#include <math.h>

#define S_LEN 2048
#define HID   2048
#define NH    32
#define NKV   8
#define HD    64
#define DQ    (NH * HD)    // 2048
#define DKV   (NKV * HD)   // 512
#define NEG_HUGE (-1e30f)

// -------- scratch (no dynamic allocation allowed) --------
__device__ float g_q[S_LEN * DQ];   // 16 MB
__device__ float g_k[S_LEN * DKV];  //  4 MB
__device__ float g_v[S_LEN * DKV];  //  4 MB
__device__ float g_o[S_LEN * DQ];   // 16 MB

// ============================================================
// C[M,N] = A[M,K] * B[N,K]^T  (both row-major, K contiguous)
// 128x128 tile, BK=16, 8x8 per thread, 256 threads
// ============================================================
__global__ __launch_bounds__(256) void gemm_nt(const float* __restrict__ A,
                                               const float* __restrict__ B,
                                               float* __restrict__ C,
                                               int M, int N, int K) {
    __shared__ float As[16][132];
    __shared__ float Bs[16][132];
    const int tid  = threadIdx.x;
    const int brow = blockIdx.y * 128;
    const int bcol = blockIdx.x * 128;
    const int tx   = tid & 15;
    const int ty   = tid >> 4;

    float acc[8][8];
#pragma unroll
    for (int i = 0; i < 8; i++)
#pragma unroll
        for (int j = 0; j < 8; j++) acc[i][j] = 0.f;

    for (int k0 = 0; k0 < K; k0 += 16) {
#pragma unroll
        for (int t = 0; t < 2; t++) {
            int idx = tid + t * 256;       // 0..511
            int r   = idx >> 2;            // 0..127
            int kc  = (idx & 3) << 2;      // 0,4,8,12
            const float4 va = *reinterpret_cast<const float4*>(&A[(size_t)(brow + r) * K + k0 + kc]);
            As[kc + 0][r] = va.x; As[kc + 1][r] = va.y;
            As[kc + 2][r] = va.z; As[kc + 3][r] = va.w;
            const float4 vb = *reinterpret_cast<const float4*>(&B[(size_t)(bcol + r) * K + k0 + kc]);
            Bs[kc + 0][r] = vb.x; Bs[kc + 1][r] = vb.y;
            Bs[kc + 2][r] = vb.z; Bs[kc + 3][r] = vb.w;
        }
        __syncthreads();

#pragma unroll 8
        for (int k = 0; k < 16; k++) {
            float a[8], b[8];
            *reinterpret_cast<float4*>(&a[0]) = *reinterpret_cast<const float4*>(&As[k][ty * 8]);
            *reinterpret_cast<float4*>(&a[4]) = *reinterpret_cast<const float4*>(&As[k][ty * 8 + 4]);
            *reinterpret_cast<float4*>(&b[0]) = *reinterpret_cast<const float4*>(&Bs[k][tx * 8]);
            *reinterpret_cast<float4*>(&b[4]) = *reinterpret_cast<const float4*>(&Bs[k][tx * 8 + 4]);
#pragma unroll
            for (int i = 0; i < 8; i++)
#pragma unroll
                for (int j = 0; j < 8; j++) acc[i][j] += a[i] * b[j];
        }
        __syncthreads();
    }

#pragma unroll
    for (int i = 0; i < 8; i++) {
        float4 v0 = make_float4(acc[i][0], acc[i][1], acc[i][2], acc[i][3]);
        float4 v1 = make_float4(acc[i][4], acc[i][5], acc[i][6], acc[i][7]);
        size_t row = (size_t)(brow + ty * 8 + i) * N + bcol + tx * 8;
        *reinterpret_cast<float4*>(&C[row])     = v0;
        *reinterpret_cast<float4*>(&C[row + 4]) = v1;
    }
}

// ============================================================
// RoPE (in place), optionally folds in attention scaling
// x: [S, nheads*64]; cos/sin: [S, 64]
// ============================================================
__global__ void rope_kernel(float* __restrict__ x,
                            const float* __restrict__ cosb,
                            const float* __restrict__ sinb,
                            int nheads, float scale) {
    int t = blockIdx.x * blockDim.x + threadIdx.x;
    int total = S_LEN * nheads * 32;
    if (t >= total) return;
    int d = t & 31;
    int h = (t >> 5) % nheads;
    int s = t / (nheads * 32);
    float c1 = cosb[s * HD + d],      s1 = sinb[s * HD + d];
    float c2 = cosb[s * HD + d + 32], s2 = sinb[s * HD + d + 32];
    size_t base = (size_t)(s * nheads + h) * HD;
    float x1 = x[base + d];
    float x2 = x[base + d + 32];
    x[base + d]      = (x1 * c1 - x2 * s1) * scale;   // rotate_half: first half = -x2
    x[base + d + 32] = (x2 * c2 + x1 * s2) * scale;   // second half = +x1
}

// ============================================================
// Causal flash attention, fp32.  One block per (q-tile of 64, head).
// 256 threads, 16x16 layout, 4x4 per thread.  P is staged through
// the K smem buffer (K dead after S is computed).
// ============================================================
__global__ __launch_bounds__(256) void flash_kernel() {
    extern __shared__ float sm[];
    float* Qs = sm;                   // 64*64
    float* Ks = sm + 4096;            // 64*65  (reused for P)
    float* Vs = sm + 4096 + 4160;     // 64*64

    const int tid  = threadIdx.x;
    const int tx   = tid & 15;
    const int ty   = tid >> 4;
    const int qt   = blockIdx.x;
    const int head = blockIdx.y;
    const int kvh  = head >> 2;       // N_REP = 4

    // load Q tile (already RoPE'd and pre-scaled)
#pragma unroll
    for (int t = 0; t < 4; t++) {
        int idx = tid + t * 256;
        int r = idx >> 4, dc = (idx & 15) << 2;
        *reinterpret_cast<float4*>(&Qs[r * 64 + dc]) =
            *reinterpret_cast<const float4*>(&g_q[(size_t)(qt * 64 + r) * DQ + head * HD + dc]);
    }

    float m[4], l[4], acc[4][4];
#pragma unroll
    for (int i = 0; i < 4; i++) {
        m[i] = NEG_HUGE; l[i] = 0.f;
#pragma unroll
        for (int j = 0; j < 4; j++) acc[i][j] = 0.f;
    }

    for (int kt = 0; kt <= qt; kt++) {
        __syncthreads();  // previous iter's P/V reads done (also covers Q load, 1st iter)
#pragma unroll
        for (int t = 0; t < 4; t++) {
            int idx = tid + t * 256;
            int r = idx >> 4, dc = (idx & 15) << 2;
            const float4 kv = *reinterpret_cast<const float4*>(
                &g_k[(size_t)(kt * 64 + r) * DKV + kvh * HD + dc]);
            Ks[r * 65 + dc + 0] = kv.x; Ks[r * 65 + dc + 1] = kv.y;
            Ks[r * 65 + dc + 2] = kv.z; Ks[r * 65 + dc + 3] = kv.w;
            *reinterpret_cast<float4*>(&Vs[r * 64 + dc]) =
                *reinterpret_cast<const float4*>(&g_v[(size_t)(kt * 64 + r) * DKV + kvh * HD + dc]);
        }
        __syncthreads();

        // S = Q K^T
        float s[4][4];
#pragma unroll
        for (int i = 0; i < 4; i++)
#pragma unroll
            for (int j = 0; j < 4; j++) s[i][j] = 0.f;

#pragma unroll 8
        for (int d = 0; d < 64; d++) {
            float q[4], kk[4];
#pragma unroll
            for (int i = 0; i < 4; i++) q[i]  = Qs[(4 * ty + i) * 64 + d];
#pragma unroll
            for (int j = 0; j < 4; j++) kk[j] = Ks[(4 * tx + j) * 65 + d];
#pragma unroll
            for (int i = 0; i < 4; i++)
#pragma unroll
                for (int j = 0; j < 4; j++) s[i][j] += q[i] * kk[j];
        }

        if (kt == qt) {  // diagonal tile: causal mask
#pragma unroll
            for (int i = 0; i < 4; i++) {
                int row = 4 * ty + i;
#pragma unroll
                for (int j = 0; j < 4; j++)
                    if (4 * tx + j > row) s[i][j] = NEG_HUGE;
            }
        }

        // online softmax (row reductions across the 16-lane tx group)
#pragma unroll
        for (int i = 0; i < 4; i++) {
            float tm = fmaxf(fmaxf(s[i][0], s[i][1]), fmaxf(s[i][2], s[i][3]));
#pragma unroll
            for (int o = 8; o >= 1; o >>= 1)
                tm = fmaxf(tm, __shfl_xor_sync(0xffffffff, tm, o));
            float mn = fmaxf(m[i], tm);
            float sc = __expf(m[i] - mn);
            float rs = 0.f;
#pragma unroll
            for (int j = 0; j < 4; j++) { s[i][j] = __expf(s[i][j] - mn); rs += s[i][j]; }
#pragma unroll
            for (int o = 8; o >= 1; o >>= 1)
                rs += __shfl_xor_sync(0xffffffff, rs, o);
            l[i] = l[i] * sc + rs;
            m[i] = mn;
#pragma unroll
            for (int j = 0; j < 4; j++) acc[i][j] *= sc;
        }

        __syncthreads();  // everyone done reading Ks
#pragma unroll
        for (int i = 0; i < 4; i++)
#pragma unroll
            for (int j = 0; j < 4; j++)
                Ks[(4 * ty + i) * 65 + 4 * tx + j] = s[i][j];  // Ks now holds P
        __syncthreads();

        // O += P V
#pragma unroll 8
        for (int c = 0; c < 64; c++) {
            float4 v = *reinterpret_cast<const float4*>(&Vs[c * 64 + tx * 4]);
#pragma unroll
            for (int i = 0; i < 4; i++) {
                float p = Ks[(4 * ty + i) * 65 + c];
                acc[i][0] += p * v.x; acc[i][1] += p * v.y;
                acc[i][2] += p * v.z; acc[i][3] += p * v.w;
            }
        }
    }

#pragma unroll
    for (int i = 0; i < 4; i++) {
        float inv = 1.f / l[i];
        float4 o = make_float4(acc[i][0] * inv, acc[i][1] * inv,
                               acc[i][2] * inv, acc[i][3] * inv);
        *reinterpret_cast<float4*>(
            &g_o[(size_t)(qt * 64 + 4 * ty + i) * DQ + head * HD + tx * 4]) = o;
    }
}

// ============================================================
extern "C" void kernel_launch(void* const* d_in, const int* in_sizes, int n_in,
                              void* d_out, int out_size) {
    const float* hs   = (const float*)d_in[0];
    const float* cosb = (const float*)d_in[1];
    const float* sinb = (const float*)d_in[2];
    // d_in[3] = attention_mask (causal) — implemented analytically
    const float* wq   = (const float*)d_in[4];
    const float* wk   = (const float*)d_in[5];
    const float* wv   = (const float*)d_in[6];
    const float* wo   = (const float*)d_in[7];
    float* out = (float*)d_out;

    float *qp, *kp, *vp, *op;
    cudaGetSymbolAddress((void**)&qp, g_q);
    cudaGetSymbolAddress((void**)&kp, g_k);
    cudaGetSymbolAddress((void**)&vp, g_v);
    cudaGetSymbolAddress((void**)&op, g_o);

    const int flash_smem = (4096 + 4160 + 4096) * (int)sizeof(float);  // 49408 B
    cudaFuncSetAttribute(flash_kernel, cudaFuncAttributeMaxDynamicSharedMemorySize, flash_smem);

    // QKV projections: C = A * W^T
    gemm_nt<<<dim3(DQ  / 128, S_LEN / 128), 256>>>(hs, wq, qp, S_LEN, DQ,  HID);
    gemm_nt<<<dim3(DKV / 128, S_LEN / 128), 256>>>(hs, wk, kp, S_LEN, DKV, HID);
    gemm_nt<<<dim3(DKV / 128, S_LEN / 128), 256>>>(hs, wv, vp, S_LEN, DKV, HID);

    // RoPE (fold softmax scaling 1/sqrt(64) into Q)
    const float scaling = 0.125f;
    rope_kernel<<<(S_LEN * NH  * 32 + 255) / 256, 256>>>(qp, cosb, sinb, NH,  scaling);
    rope_kernel<<<(S_LEN * NKV * 32 + 255) / 256, 256>>>(kp, cosb, sinb, NKV, 1.0f);

    // causal flash attention
    flash_kernel<<<dim3(S_LEN / 64, NH), 256, flash_smem>>>();

    // output projection
    gemm_nt<<<dim3(HID / 128, S_LEN / 128), 256>>>(op, wo, out, S_LEN, HID, HID);
}

// round 2
// speedup vs baseline: 1.8511x; 1.8511x over previous
#include <cuda_runtime.h>
#include <stdint.h>
#include <math.h>

#define S_LEN 2048
#define HID   2048
#define NH    32
#define NKV   8
#define HD    64
#define DQ    (NH * HD)    // 2048
#define DKV   (NKV * HD)   // 512
#define NEG_HUGE (-1e30f)

// -------- scratch (no dynamic allocation allowed) --------
__device__ float g_q[S_LEN * DQ];   // 16 MB
__device__ float g_k[S_LEN * DKV];  //  4 MB
__device__ float g_v[S_LEN * DKV];  //  4 MB
__device__ float g_o[S_LEN * DQ];   // 16 MB

// ============================================================
// TF32 helpers
// ============================================================
__device__ __forceinline__ uint32_t f2tf32(float x) {
    uint32_t u;
    asm("cvt.rna.tf32.f32 %0, %1;" : "=r"(u) : "f"(x));
    return u;
}

__device__ __forceinline__ void mma_tf32(float c[4], const uint32_t a[4], const uint32_t b[2]) {
    asm volatile(
        "mma.sync.aligned.m16n8k8.row.col.f32.tf32.tf32.f32 "
        "{%0,%1,%2,%3}, {%4,%5,%6,%7}, {%8,%9}, {%0,%1,%2,%3};"
        : "+f"(c[0]), "+f"(c[1]), "+f"(c[2]), "+f"(c[3])
        : "r"(a[0]), "r"(a[1]), "r"(a[2]), "r"(a[3]),
          "r"(b[0]), "r"(b[1]));
}

__device__ __forceinline__ void cp_async16(uint32_t smem_dst, const void* gmem_src) {
    asm volatile("cp.async.cg.shared.global [%0], [%1], 16;" :: "r"(smem_dst), "l"(gmem_src));
}

// ============================================================
// C[M,N] = A[M,K] * B[N,K]^T  (row-major, K contiguous)
// TF32 tensor cores. 128x128 tile, BK=32, 8 warps.
// Warp grid 2(m) x 4(n); warp tile 64x32 -> 4 m-frag x 4 n-frag of m16n8k8.
// Smem: padded stride 36 floats -> conflict-free fragment loads.
// Double-buffered via cp.async.
// ============================================================
#define GK_PAD 36
#define GK_TILE (128 * GK_PAD)   // floats per A or B buffer

__global__ __launch_bounds__(256) void gemm_tf32(const float* __restrict__ A,
                                                 const float* __restrict__ B,
                                                 float* __restrict__ C,
                                                 int M, int N, int K) {
    extern __shared__ float sm[];
    const int tid    = threadIdx.x;
    const int lane   = tid & 31;
    const int wid    = tid >> 5;
    const int warp_m = wid >> 2;          // 0..1
    const int warp_n = wid & 3;           // 0..3
    const int g      = lane >> 2;         // groupID 0..7
    const int cg     = lane & 3;          // thread-in-group 0..3
    const int brow   = blockIdx.y * 128;
    const int bcol   = blockIdx.x * 128;

    float acc[4][4][4];
#pragma unroll
    for (int i = 0; i < 4; i++)
#pragma unroll
        for (int j = 0; j < 4; j++)
#pragma unroll
            for (int t = 0; t < 4; t++) acc[i][j][t] = 0.f;

    // prefetch helper (inlined twice via lambda-like macro pattern)
    auto prefetch = [&](int stage, int k0) {
        float* As = sm + stage * (2 * GK_TILE);
        float* Bs = As + GK_TILE;
        uint32_t as_base = (uint32_t)__cvta_generic_to_shared(As);
        uint32_t bs_base = (uint32_t)__cvta_generic_to_shared(Bs);
#pragma unroll
        for (int i = 0; i < 4; i++) {
            int idx = i * 256 + tid;       // 0..1023
            int r   = idx >> 3;            // 0..127
            int c4  = idx & 7;             // float4 index within 32 floats
            cp_async16(as_base + (r * GK_PAD + c4 * 4) * 4,
                       &A[(size_t)(brow + r) * K + k0 + c4 * 4]);
            cp_async16(bs_base + (r * GK_PAD + c4 * 4) * 4,
                       &B[(size_t)(bcol + r) * K + k0 + c4 * 4]);
        }
        asm volatile("cp.async.commit_group;");
    };

    int stage = 0;
    prefetch(0, 0);

    for (int k0 = 0; k0 < K; k0 += 32) {
        const bool has_next = (k0 + 32) < K;
        if (has_next) prefetch(stage ^ 1, k0 + 32);

        if (has_next) asm volatile("cp.async.wait_group 1;");
        else          asm volatile("cp.async.wait_group 0;");
        __syncthreads();

        const float* As = sm + stage * (2 * GK_TILE);
        const float* Bs = As + GK_TILE;

#pragma unroll
        for (int kk = 0; kk < 4; kk++) {
            const int kb = kk * 8;
            uint32_t Af[4][4], Bf[4][2];
#pragma unroll
            for (int mt = 0; mt < 4; mt++) {
                const float* p = &As[(warp_m * 64 + mt * 16 + g) * GK_PAD + kb + cg];
                Af[mt][0] = f2tf32(p[0]);
                Af[mt][1] = f2tf32(p[8 * GK_PAD]);
                Af[mt][2] = f2tf32(p[4]);
                Af[mt][3] = f2tf32(p[8 * GK_PAD + 4]);
            }
#pragma unroll
            for (int nt = 0; nt < 4; nt++) {
                const float* p = &Bs[(warp_n * 32 + nt * 8 + g) * GK_PAD + kb + cg];
                Bf[nt][0] = f2tf32(p[0]);
                Bf[nt][1] = f2tf32(p[4]);
            }
#pragma unroll
            for (int mt = 0; mt < 4; mt++)
#pragma unroll
                for (int nt = 0; nt < 4; nt++)
                    mma_tf32(acc[mt][nt], Af[mt], Bf[nt]);
        }
        __syncthreads();
        stage ^= 1;
    }

    // epilogue
#pragma unroll
    for (int mt = 0; mt < 4; mt++) {
#pragma unroll
        for (int nt = 0; nt < 4; nt++) {
            int row0 = brow + warp_m * 64 + mt * 16 + g;
            int col  = bcol + warp_n * 32 + nt * 8 + 2 * cg;
            float2 v0 = make_float2(acc[mt][nt][0], acc[mt][nt][1]);
            float2 v1 = make_float2(acc[mt][nt][2], acc[mt][nt][3]);
            *reinterpret_cast<float2*>(&C[(size_t)row0 * N + col])       = v0;
            *reinterpret_cast<float2*>(&C[(size_t)(row0 + 8) * N + col]) = v1;
        }
    }
}

// ============================================================
// RoPE (in place), optionally folds in attention scaling
// ============================================================
__global__ void rope_kernel(float* __restrict__ x,
                            const float* __restrict__ cosb,
                            const float* __restrict__ sinb,
                            int nheads, float scale) {
    int t = blockIdx.x * blockDim.x + threadIdx.x;
    int total = S_LEN * nheads * 32;
    if (t >= total) return;
    int d = t & 31;
    int h = (t >> 5) % nheads;
    int s = t / (nheads * 32);
    float c1 = cosb[s * HD + d],      s1 = sinb[s * HD + d];
    float c2 = cosb[s * HD + d + 32], s2 = sinb[s * HD + d + 32];
    size_t base = (size_t)(s * nheads + h) * HD;
    float x1 = x[base + d];
    float x2 = x[base + d + 32];
    x[base + d]      = (x1 * c1 - x2 * s1) * scale;
    x[base + d + 32] = (x2 * c2 + x1 * s2) * scale;
}

// ============================================================
// Causal flash attention, fp32 (unchanged from R1 baseline)
// ============================================================
__global__ __launch_bounds__(256) void flash_kernel() {
    extern __shared__ float smf[];
    float* Qs = smf;
    float* Ks = smf + 4096;
    float* Vs = smf + 4096 + 4160;

    const int tid  = threadIdx.x;
    const int tx   = tid & 15;
    const int ty   = tid >> 4;
    const int qt   = blockIdx.x;
    const int head = blockIdx.y;
    const int kvh  = head >> 2;

#pragma unroll
    for (int t = 0; t < 4; t++) {
        int idx = tid + t * 256;
        int r = idx >> 4, dc = (idx & 15) << 2;
        *reinterpret_cast<float4*>(&Qs[r * 64 + dc]) =
            *reinterpret_cast<const float4*>(&g_q[(size_t)(qt * 64 + r) * DQ + head * HD + dc]);
    }

    float m[4], l[4], acc[4][4];
#pragma unroll
    for (int i = 0; i < 4; i++) {
        m[i] = NEG_HUGE; l[i] = 0.f;
#pragma unroll
        for (int j = 0; j < 4; j++) acc[i][j] = 0.f;
    }

    for (int kt = 0; kt <= qt; kt++) {
        __syncthreads();
#pragma unroll
        for (int t = 0; t < 4; t++) {
            int idx = tid + t * 256;
            int r = idx >> 4, dc = (idx & 15) << 2;
            const float4 kv = *reinterpret_cast<const float4*>(
                &g_k[(size_t)(kt * 64 + r) * DKV + kvh * HD + dc]);
            Ks[r * 65 + dc + 0] = kv.x; Ks[r * 65 + dc + 1] = kv.y;
            Ks[r * 65 + dc + 2] = kv.z; Ks[r * 65 + dc + 3] = kv.w;
            *reinterpret_cast<float4*>(&Vs[r * 64 + dc]) =
                *reinterpret_cast<const float4*>(&g_v[(size_t)(kt * 64 + r) * DKV + kvh * HD + dc]);
        }
        __syncthreads();

        float s[4][4];
#pragma unroll
        for (int i = 0; i < 4; i++)
#pragma unroll
            for (int j = 0; j < 4; j++) s[i][j] = 0.f;

#pragma unroll 8
        for (int d = 0; d < 64; d++) {
            float q[4], kk[4];
#pragma unroll
            for (int i = 0; i < 4; i++) q[i]  = Qs[(4 * ty + i) * 64 + d];
#pragma unroll
            for (int j = 0; j < 4; j++) kk[j] = Ks[(4 * tx + j) * 65 + d];
#pragma unroll
            for (int i = 0; i < 4; i++)
#pragma unroll
                for (int j = 0; j < 4; j++) s[i][j] += q[i] * kk[j];
        }

        if (kt == qt) {
#pragma unroll
            for (int i = 0; i < 4; i++) {
                int row = 4 * ty + i;
#pragma unroll
                for (int j = 0; j < 4; j++)
                    if (4 * tx + j > row) s[i][j] = NEG_HUGE;
            }
        }

#pragma unroll
        for (int i = 0; i < 4; i++) {
            float tm = fmaxf(fmaxf(s[i][0], s[i][1]), fmaxf(s[i][2], s[i][3]));
#pragma unroll
            for (int o = 8; o >= 1; o >>= 1)
                tm = fmaxf(tm, __shfl_xor_sync(0xffffffff, tm, o));
            float mn = fmaxf(m[i], tm);
            float sc = __expf(m[i] - mn);
            float rs = 0.f;
#pragma unroll
            for (int j = 0; j < 4; j++) { s[i][j] = __expf(s[i][j] - mn); rs += s[i][j]; }
#pragma unroll
            for (int o = 8; o >= 1; o >>= 1)
                rs += __shfl_xor_sync(0xffffffff, rs, o);
            l[i] = l[i] * sc + rs;
            m[i] = mn;
#pragma unroll
            for (int j = 0; j < 4; j++) acc[i][j] *= sc;
        }

        __syncthreads();
#pragma unroll
        for (int i = 0; i < 4; i++)
#pragma unroll
            for (int j = 0; j < 4; j++)
                Ks[(4 * ty + i) * 65 + 4 * tx + j] = s[i][j];
        __syncthreads();

#pragma unroll 8
        for (int c = 0; c < 64; c++) {
            float4 v = *reinterpret_cast<const float4*>(&Vs[c * 64 + tx * 4]);
#pragma unroll
            for (int i = 0; i < 4; i++) {
                float p = Ks[(4 * ty + i) * 65 + c];
                acc[i][0] += p * v.x; acc[i][1] += p * v.y;
                acc[i][2] += p * v.z; acc[i][3] += p * v.w;
            }
        }
    }

#pragma unroll
    for (int i = 0; i < 4; i++) {
        float inv = 1.f / l[i];
        float4 o = make_float4(acc[i][0] * inv, acc[i][1] * inv,
                               acc[i][2] * inv, acc[i][3] * inv);
        *reinterpret_cast<float4*>(
            &g_o[(size_t)(qt * 64 + 4 * ty + i) * DQ + head * HD + tx * 4]) = o;
    }
}

// ============================================================
extern "C" void kernel_launch(void* const* d_in, const int* in_sizes, int n_in,
                              void* d_out, int out_size) {
    const float* hs   = (const float*)d_in[0];
    const float* cosb = (const float*)d_in[1];
    const float* sinb = (const float*)d_in[2];
    // d_in[3] = attention_mask (causal) — implemented analytically
    const float* wq   = (const float*)d_in[4];
    const float* wk   = (const float*)d_in[5];
    const float* wv   = (const float*)d_in[6];
    const float* wo   = (const float*)d_in[7];
    float* out = (float*)d_out;

    float *qp, *kp, *vp, *op;
    cudaGetSymbolAddress((void**)&qp, g_q);
    cudaGetSymbolAddress((void**)&kp, g_k);
    cudaGetSymbolAddress((void**)&vp, g_v);
    cudaGetSymbolAddress((void**)&op, g_o);

    const int gemm_smem  = 2 * 2 * GK_TILE * (int)sizeof(float);        // 73728 B
    const int flash_smem = (4096 + 4160 + 4096) * (int)sizeof(float);   // 49408 B
    cudaFuncSetAttribute(gemm_tf32,  cudaFuncAttributeMaxDynamicSharedMemorySize, gemm_smem);
    cudaFuncSetAttribute(flash_kernel, cudaFuncAttributeMaxDynamicSharedMemorySize, flash_smem);

    // QKV projections on tensor cores
    gemm_tf32<<<dim3(DQ  / 128, S_LEN / 128), 256, gemm_smem>>>(hs, wq, qp, S_LEN, DQ,  HID);
    gemm_tf32<<<dim3(DKV / 128, S_LEN / 128), 256, gemm_smem>>>(hs, wk, kp, S_LEN, DKV, HID);
    gemm_tf32<<<dim3(DKV / 128, S_LEN / 128), 256, gemm_smem>>>(hs, wv, vp, S_LEN, DKV, HID);

    // RoPE (fold softmax scaling 1/sqrt(64) into Q)
    const float scaling = 0.125f;
    rope_kernel<<<(S_LEN * NH  * 32 + 255) / 256, 256>>>(qp, cosb, sinb, NH,  scaling);
    rope_kernel<<<(S_LEN * NKV * 32 + 255) / 256, 256>>>(kp, cosb, sinb, NKV, 1.0f);

    // causal flash attention (fp32, unchanged)
    flash_kernel<<<dim3(S_LEN / 64, NH), 256, flash_smem>>>();

    // output projection on tensor cores
    gemm_tf32<<<dim3(HID / 128, S_LEN / 128), 256, gemm_smem>>>(op, wo, out, S_LEN, HID, HID);
}

// round 4
// speedup vs baseline: 3.0423x; 1.6436x over previous
#include <cuda_runtime.h>
#include <stdint.h>
#include <math.h>

#define S_LEN 2048
#define HID   2048
#define NH    32
#define NKV   8
#define HD    64
#define DQ    (NH * HD)    // 2048
#define DKV   (NKV * HD)   // 512
#define NEG_HUGE (-1e30f)

// -------- scratch (no dynamic allocation allowed) --------
__device__ float g_q[S_LEN * DQ];   // 16 MB
__device__ float g_k[S_LEN * DKV];  //  4 MB
__device__ float g_v[S_LEN * DKV];  //  4 MB
__device__ float g_o[S_LEN * DQ];   // 16 MB

// ============================================================
// TF32 helpers
// ============================================================
__device__ __forceinline__ uint32_t f2tf32(float x) {
    uint32_t u;
    asm("cvt.rna.tf32.f32 %0, %1;" : "=r"(u) : "f"(x));
    return u;
}

__device__ __forceinline__ void mma_tf32(float c[4], const uint32_t a[4], const uint32_t b[2]) {
    asm volatile(
        "mma.sync.aligned.m16n8k8.row.col.f32.tf32.tf32.f32 "
        "{%0,%1,%2,%3}, {%4,%5,%6,%7}, {%8,%9}, {%0,%1,%2,%3};"
        : "+f"(c[0]), "+f"(c[1]), "+f"(c[2]), "+f"(c[3])
        : "r"(a[0]), "r"(a[1]), "r"(a[2]), "r"(a[3]),
          "r"(b[0]), "r"(b[1]));
}

__device__ __forceinline__ void cp_async16(uint32_t smem_dst, const void* gmem_src) {
    asm volatile("cp.async.cg.shared.global [%0], [%1], 16;" :: "r"(smem_dst), "l"(gmem_src));
}

// ============================================================
// C[M,N] = A[M,K] * B[N,K]^T  — TF32 tensor cores
// 128x128 tile, BK=32, 8 warps, double-buffered cp.async
// ============================================================
#define GK_PAD 36
#define GK_TILE (128 * GK_PAD)

__global__ __launch_bounds__(256) void gemm_tf32(const float* __restrict__ A,
                                                 const float* __restrict__ B,
                                                 float* __restrict__ C,
                                                 int M, int N, int K) {
    extern __shared__ float sm[];
    const int tid    = threadIdx.x;
    const int lane   = tid & 31;
    const int wid    = tid >> 5;
    const int warp_m = wid >> 2;
    const int warp_n = wid & 3;
    const int g      = lane >> 2;
    const int cg     = lane & 3;
    const int brow   = blockIdx.y * 128;
    const int bcol   = blockIdx.x * 128;

    float acc[4][4][4];
#pragma unroll
    for (int i = 0; i < 4; i++)
#pragma unroll
        for (int j = 0; j < 4; j++)
#pragma unroll
            for (int t = 0; t < 4; t++) acc[i][j][t] = 0.f;

    auto prefetch = [&](int stage, int k0) {
        float* As = sm + stage * (2 * GK_TILE);
        float* Bs = As + GK_TILE;
        uint32_t as_base = (uint32_t)__cvta_generic_to_shared(As);
        uint32_t bs_base = (uint32_t)__cvta_generic_to_shared(Bs);
#pragma unroll
        for (int i = 0; i < 4; i++) {
            int idx = i * 256 + tid;
            int r   = idx >> 3;
            int c4  = idx & 7;
            cp_async16(as_base + (r * GK_PAD + c4 * 4) * 4,
                       &A[(size_t)(brow + r) * K + k0 + c4 * 4]);
            cp_async16(bs_base + (r * GK_PAD + c4 * 4) * 4,
                       &B[(size_t)(bcol + r) * K + k0 + c4 * 4]);
        }
        asm volatile("cp.async.commit_group;");
    };

    int stage = 0;
    prefetch(0, 0);

    for (int k0 = 0; k0 < K; k0 += 32) {
        const bool has_next = (k0 + 32) < K;
        if (has_next) prefetch(stage ^ 1, k0 + 32);

        if (has_next) asm volatile("cp.async.wait_group 1;");
        else          asm volatile("cp.async.wait_group 0;");
        __syncthreads();

        const float* As = sm + stage * (2 * GK_TILE);
        const float* Bs = As + GK_TILE;

#pragma unroll
        for (int kk = 0; kk < 4; kk++) {
            const int kb = kk * 8;
            uint32_t Af[4][4], Bf[4][2];
#pragma unroll
            for (int mt = 0; mt < 4; mt++) {
                const float* p = &As[(warp_m * 64 + mt * 16 + g) * GK_PAD + kb + cg];
                Af[mt][0] = f2tf32(p[0]);
                Af[mt][1] = f2tf32(p[8 * GK_PAD]);
                Af[mt][2] = f2tf32(p[4]);
                Af[mt][3] = f2tf32(p[8 * GK_PAD + 4]);
            }
#pragma unroll
            for (int nt = 0; nt < 4; nt++) {
                const float* p = &Bs[(warp_n * 32 + nt * 8 + g) * GK_PAD + kb + cg];
                Bf[nt][0] = f2tf32(p[0]);
                Bf[nt][1] = f2tf32(p[4]);
            }
#pragma unroll
            for (int mt = 0; mt < 4; mt++)
#pragma unroll
                for (int nt = 0; nt < 4; nt++)
                    mma_tf32(acc[mt][nt], Af[mt], Bf[nt]);
        }
        __syncthreads();
        stage ^= 1;
    }

#pragma unroll
    for (int mt = 0; mt < 4; mt++) {
#pragma unroll
        for (int nt = 0; nt < 4; nt++) {
            int row0 = brow + warp_m * 64 + mt * 16 + g;
            int col  = bcol + warp_n * 32 + nt * 8 + 2 * cg;
            float2 v0 = make_float2(acc[mt][nt][0], acc[mt][nt][1]);
            float2 v1 = make_float2(acc[mt][nt][2], acc[mt][nt][3]);
            *reinterpret_cast<float2*>(&C[(size_t)row0 * N + col])       = v0;
            *reinterpret_cast<float2*>(&C[(size_t)(row0 + 8) * N + col]) = v1;
        }
    }
}

// ============================================================
// RoPE (in place), folds attention scaling into Q
// ============================================================
__global__ void rope_kernel(float* __restrict__ x,
                            const float* __restrict__ cosb,
                            const float* __restrict__ sinb,
                            int nheads, float scale) {
    int t = blockIdx.x * blockDim.x + threadIdx.x;
    int total = S_LEN * nheads * 32;
    if (t >= total) return;
    int d = t & 31;
    int h = (t >> 5) % nheads;
    int s = t / (nheads * 32);
    float c1 = cosb[s * HD + d],      s1 = sinb[s * HD + d];
    float c2 = cosb[s * HD + d + 32], s2 = sinb[s * HD + d + 32];
    size_t base = (size_t)(s * nheads + h) * HD;
    float x1 = x[base + d];
    float x2 = x[base + d + 32];
    x[base + d]      = (x1 * c1 - x2 * s1) * scale;
    x[base + d + 32] = (x2 * c2 + x1 * s2) * scale;
}

// ============================================================
// TF32 tensor-core causal flash attention.
// BQ=128, BK=64. 8 warps; warp w owns q-rows [w*16, w*16+16).
// Q held as tf32 A-fragments in registers. K/V double-buffered cp.async.
// P re-fragmented via intra-quad shuffles (warp-local PV).
// ============================================================
#define KS_STR 68          // bank map 4g+cg : conflict-free
#define VS_STR 72          // bank map 8cg+g : conflict-free
#define FSTAGE (64 * KS_STR + 64 * VS_STR)   // 8960 floats per stage

__global__ __launch_bounds__(256) void flash_tf32() {
    extern __shared__ float sm[];
    const int tid  = threadIdx.x;
    const int lane = tid & 31;
    const int w    = tid >> 5;
    const int g    = lane >> 2;
    const int cg   = lane & 3;
    const int qt   = gridDim.x - 1 - blockIdx.x;   // heavy tiles first
    const int head = blockIdx.y;
    const int kvh  = head >> 2;
    const int row0 = qt * 128 + w * 16 + g;        // global q row (second row = +8)

    // ---- Q fragments (loaded once, already RoPE'd + pre-scaled) ----
    uint32_t qf[8][4];
    {
        const float* q0 = &g_q[(size_t)row0 * DQ + head * HD];
        const float* q1 = q0 + 8 * DQ;
#pragma unroll
        for (int ks = 0; ks < 8; ks++) {
            qf[ks][0] = f2tf32(q0[8 * ks + cg]);
            qf[ks][1] = f2tf32(q1[8 * ks + cg]);
            qf[ks][2] = f2tf32(q0[8 * ks + cg + 4]);
            qf[ks][3] = f2tf32(q1[8 * ks + cg + 4]);
        }
    }

    float oacc[8][4];
#pragma unroll
    for (int nf = 0; nf < 8; nf++)
#pragma unroll
        for (int t = 0; t < 4; t++) oacc[nf][t] = 0.f;
    float m0 = NEG_HUGE, m1 = NEG_HUGE, l0 = 0.f, l1 = 0.f;

    auto prefetch = [&](int kb, int s) {
        float* Ks = sm + s * FSTAGE;
        float* Vs = Ks + 64 * KS_STR;
        uint32_t ka = (uint32_t)__cvta_generic_to_shared(Ks);
        uint32_t va = (uint32_t)__cvta_generic_to_shared(Vs);
#pragma unroll
        for (int t = 0; t < 4; t++) {
            int idx = t * 256 + tid;   // 0..1023
            int r   = idx >> 4;        // 0..63
            int c4  = (idx & 15) * 4;  // 0..60
            cp_async16(ka + (r * KS_STR + c4) * 4,
                       &g_k[(size_t)(kb * 64 + r) * DKV + kvh * HD + c4]);
            cp_async16(va + (r * VS_STR + c4) * 4,
                       &g_v[(size_t)(kb * 64 + r) * DKV + kvh * HD + c4]);
        }
        asm volatile("cp.async.commit_group;");
    };

    const int nkb = 2 * qt + 2;
    prefetch(0, 0);

    for (int kb = 0; kb < nkb; kb++) {
        const int s = kb & 1;
        if (kb + 1 < nkb) {
            prefetch(kb + 1, s ^ 1);
            asm volatile("cp.async.wait_group 1;");
        } else {
            asm volatile("cp.async.wait_group 0;");
        }
        __syncthreads();

        const float* Ks = sm + s * FSTAGE;
        const float* Vs = Ks + 64 * KS_STR;

        // warps 0-3 have nothing unmasked in the final half-tile
        const bool active = !(w < 4 && kb == 2 * qt + 1);
        if (active) {
            // ---- S = Q K^T ----
            float sacc[8][4];
#pragma unroll
            for (int nf = 0; nf < 8; nf++)
#pragma unroll
                for (int t = 0; t < 4; t++) sacc[nf][t] = 0.f;

#pragma unroll
            for (int ks = 0; ks < 8; ks++) {
#pragma unroll
                for (int nf = 0; nf < 8; nf++) {
                    uint32_t b[2];
                    const float* p = &Ks[(nf * 8 + g) * KS_STR + ks * 8 + cg];
                    b[0] = f2tf32(p[0]);
                    b[1] = f2tf32(p[4]);
                    mma_tf32(sacc[nf], qf[ks], b);
                }
            }

            // ---- causal mask (only possible on the last two k-blocks) ----
            if (kb >= 2 * qt) {
#pragma unroll
                for (int nf = 0; nf < 8; nf++) {
                    int c = kb * 64 + nf * 8 + 2 * cg;
                    if (c     > row0)     sacc[nf][0] = NEG_HUGE;
                    if (c + 1 > row0)     sacc[nf][1] = NEG_HUGE;
                    if (c     > row0 + 8) sacc[nf][2] = NEG_HUGE;
                    if (c + 1 > row0 + 8) sacc[nf][3] = NEG_HUGE;
                }
            }

            // ---- online softmax (rows g and g+8, warp-local) ----
            float tm0 = NEG_HUGE, tm1 = NEG_HUGE;
#pragma unroll
            for (int nf = 0; nf < 8; nf++) {
                tm0 = fmaxf(tm0, fmaxf(sacc[nf][0], sacc[nf][1]));
                tm1 = fmaxf(tm1, fmaxf(sacc[nf][2], sacc[nf][3]));
            }
            tm0 = fmaxf(tm0, __shfl_xor_sync(0xffffffff, tm0, 1));
            tm0 = fmaxf(tm0, __shfl_xor_sync(0xffffffff, tm0, 2));
            tm1 = fmaxf(tm1, __shfl_xor_sync(0xffffffff, tm1, 1));
            tm1 = fmaxf(tm1, __shfl_xor_sync(0xffffffff, tm1, 2));

            const float mn0 = fmaxf(m0, tm0);
            const float mn1 = fmaxf(m1, tm1);
            const float sc0 = __expf(m0 - mn0);
            const float sc1 = __expf(m1 - mn1);

            float rs0 = 0.f, rs1 = 0.f;
#pragma unroll
            for (int nf = 0; nf < 8; nf++) {
                sacc[nf][0] = __expf(sacc[nf][0] - mn0);
                sacc[nf][1] = __expf(sacc[nf][1] - mn0);
                sacc[nf][2] = __expf(sacc[nf][2] - mn1);
                sacc[nf][3] = __expf(sacc[nf][3] - mn1);
                rs0 += sacc[nf][0] + sacc[nf][1];
                rs1 += sacc[nf][2] + sacc[nf][3];
            }
            rs0 += __shfl_xor_sync(0xffffffff, rs0, 1);
            rs0 += __shfl_xor_sync(0xffffffff, rs0, 2);
            rs1 += __shfl_xor_sync(0xffffffff, rs1, 1);
            rs1 += __shfl_xor_sync(0xffffffff, rs1, 2);

            l0 = l0 * sc0 + rs0;  m0 = mn0;
            l1 = l1 * sc1 + rs1;  m1 = mn1;
#pragma unroll
            for (int nf = 0; nf < 8; nf++) {
                oacc[nf][0] *= sc0; oacc[nf][1] *= sc0;
                oacc[nf][2] *= sc1; oacc[nf][3] *= sc1;
            }

            // ---- O += P V : re-fragment P via intra-quad shuffles ----
            const int base = lane & ~3;
            const int s0l  = base + (cg >> 1);
            const int s1l  = s0l + 2;
            const bool odd = (cg & 1);
#pragma unroll
            for (int ks = 0; ks < 8; ks++) {
                const uint32_t c0 = f2tf32(sacc[ks][0]);
                const uint32_t c1 = f2tf32(sacc[ks][1]);
                const uint32_t c2 = f2tf32(sacc[ks][2]);
                const uint32_t c3 = f2tf32(sacc[ks][3]);
                uint32_t a[4];
                {
                    uint32_t t00 = __shfl_sync(0xffffffff, c0, s0l);
                    uint32_t t01 = __shfl_sync(0xffffffff, c1, s0l);
                    uint32_t t10 = __shfl_sync(0xffffffff, c0, s1l);
                    uint32_t t11 = __shfl_sync(0xffffffff, c1, s1l);
                    a[0] = odd ? t01 : t00;
                    a[2] = odd ? t11 : t10;
                    uint32_t u00 = __shfl_sync(0xffffffff, c2, s0l);
                    uint32_t u01 = __shfl_sync(0xffffffff, c3, s0l);
                    uint32_t u10 = __shfl_sync(0xffffffff, c2, s1l);
                    uint32_t u11 = __shfl_sync(0xffffffff, c3, s1l);
                    a[1] = odd ? u01 : u00;
                    a[3] = odd ? u11 : u10;
                }
#pragma unroll
                for (int nf = 0; nf < 8; nf++) {
                    uint32_t b[2];
                    const float* vp = &Vs[(ks * 8 + cg) * VS_STR + nf * 8 + g];
                    b[0] = f2tf32(vp[0]);
                    b[1] = f2tf32(vp[4 * VS_STR]);
                    mma_tf32(oacc[nf], a, b);
                }
            }
        }
        __syncthreads();   // buffer s free for the prefetch two iterations out
    }

    // ---- normalize + store ----
    const float inv0 = 1.f / l0;
    const float inv1 = 1.f / l1;
    float* o0 = &g_o[(size_t)row0 * DQ + head * HD];
    float* o1 = o0 + 8 * DQ;
#pragma unroll
    for (int nf = 0; nf < 8; nf++) {
        *reinterpret_cast<float2*>(&o0[nf * 8 + 2 * cg]) =
            make_float2(oacc[nf][0] * inv0, oacc[nf][1] * inv0);
        *reinterpret_cast<float2*>(&o1[nf * 8 + 2 * cg]) =
            make_float2(oacc[nf][2] * inv1, oacc[nf][3] * inv1);
    }
}

// ============================================================
extern "C" void kernel_launch(void* const* d_in, const int* in_sizes, int n_in,
                              void* d_out, int out_size) {
    const float* hs   = (const float*)d_in[0];
    const float* cosb = (const float*)d_in[1];
    const float* sinb = (const float*)d_in[2];
    // d_in[3] = attention_mask (causal) — implemented analytically
    const float* wq   = (const float*)d_in[4];
    const float* wk   = (const float*)d_in[5];
    const float* wv   = (const float*)d_in[6];
    const float* wo   = (const float*)d_in[7];
    float* out = (float*)d_out;

    float *qp, *kp, *vp, *op;
    cudaGetSymbolAddress((void**)&qp, g_q);
    cudaGetSymbolAddress((void**)&kp, g_k);
    cudaGetSymbolAddress((void**)&vp, g_v);
    cudaGetSymbolAddress((void**)&op, g_o);

    const int gemm_smem  = 2 * 2 * GK_TILE * (int)sizeof(float);   // 73728 B
    const int flash_smem = 2 * FSTAGE * (int)sizeof(float);        // 71680 B
    cudaFuncSetAttribute(gemm_tf32,  cudaFuncAttributeMaxDynamicSharedMemorySize, gemm_smem);
    cudaFuncSetAttribute(flash_tf32, cudaFuncAttributeMaxDynamicSharedMemorySize, flash_smem);

    // QKV projections on tensor cores
    gemm_tf32<<<dim3(DQ  / 128, S_LEN / 128), 256, gemm_smem>>>(hs, wq, qp, S_LEN, DQ,  HID);
    gemm_tf32<<<dim3(DKV / 128, S_LEN / 128), 256, gemm_smem>>>(hs, wk, kp, S_LEN, DKV, HID);
    gemm_tf32<<<dim3(DKV / 128, S_LEN / 128), 256, gemm_smem>>>(hs, wv, vp, S_LEN, DKV, HID);

    // RoPE (fold softmax scaling 1/sqrt(64) into Q)
    const float scaling = 0.125f;
    rope_kernel<<<(S_LEN * NH  * 32 + 255) / 256, 256>>>(qp, cosb, sinb, NH,  scaling);
    rope_kernel<<<(S_LEN * NKV * 32 + 255) / 256, 256>>>(kp, cosb, sinb, NKV, 1.0f);

    // TF32 tensor-core causal flash attention
    flash_tf32<<<dim3(S_LEN / 128, NH), 256, flash_smem>>>();

    // output projection on tensor cores
    gemm_tf32<<<dim3(HID / 128, S_LEN / 128), 256, gemm_smem>>>(op, wo, out, S_LEN, HID, HID);
}

// round 7
// speedup vs baseline: 3.5564x; 1.1690x over previous
#include <cuda_runtime.h>
#include <stdint.h>
#include <math.h>

#define S_LEN 2048
#define HID   2048
#define NH    32
#define NKV   8
#define HD    64
#define DQ    (NH * HD)    // 2048
#define DKV   (NKV * HD)   // 512
#define NEG_HUGE (-1e30f)

// -------- scratch (no dynamic allocation allowed) --------
__device__ float g_q[S_LEN * DQ];   // 16 MB
__device__ float g_k[S_LEN * DKV];  //  4 MB
__device__ float g_v[S_LEN * DKV];  //  4 MB
__device__ float g_o[S_LEN * DQ];   // 16 MB

// ============================================================
// TF32 helpers
// ============================================================
__device__ __forceinline__ uint32_t f2tf32(float x) {
    uint32_t u;
    asm("cvt.rna.tf32.f32 %0, %1;" : "=r"(u) : "f"(x));
    return u;
}

__device__ __forceinline__ void mma_tf32(float c[4], const uint32_t a[4], const uint32_t b[2]) {
    asm volatile(
        "mma.sync.aligned.m16n8k8.row.col.f32.tf32.tf32.f32 "
        "{%0,%1,%2,%3}, {%4,%5,%6,%7}, {%8,%9}, {%0,%1,%2,%3};"
        : "+f"(c[0]), "+f"(c[1]), "+f"(c[2]), "+f"(c[3])
        : "r"(a[0]), "r"(a[1]), "r"(a[2]), "r"(a[3]),
          "r"(b[0]), "r"(b[1]));
}

__device__ __forceinline__ void cp_async16(uint32_t smem_dst, const void* gmem_src) {
    asm volatile("cp.async.cg.shared.global [%0], [%1], 16;" :: "r"(smem_dst), "l"(gmem_src));
}

#define GK_PAD 36
#define GK_TILE (128 * GK_PAD)

// ============================================================
// Fused QKV projection + RoPE + scaling, one launch.
// Grid x: 0..15 -> Q cols, 16..19 -> K cols, 20..23 -> V cols.
// Warp layout 4(m) x 2(n): warp tile 32x64 = one full head wide,
// so RoPE pairs (d, d+32) live in acc[mt][nt] / acc[mt][nt+4].
// ============================================================
__global__ __launch_bounds__(256) void qkv_gemm(const float* __restrict__ A,
                                                const float* __restrict__ wq,
                                                const float* __restrict__ wk,
                                                const float* __restrict__ wv,
                                                const float* __restrict__ cosb,
                                                const float* __restrict__ sinb) {
    extern __shared__ float sm[];
    const int tid    = threadIdx.x;
    const int lane   = tid & 31;
    const int wid    = tid >> 5;
    const int warp_m = wid & 3;           // 0..3
    const int warp_n = wid >> 2;          // 0..1
    const int g      = lane >> 2;
    const int cg     = lane & 3;
    const int brow   = blockIdx.y * 128;
    const int bcol   = blockIdx.x * 128;

    const int seg = (bcol < DQ) ? 0 : ((bcol < DQ + DKV) ? 1 : 2);
    const int segbase = (seg == 0) ? 0 : ((seg == 1) ? DQ : DQ + DKV);
    const int out_col = bcol - segbase;
    const int out_ld  = (seg == 0) ? DQ : DKV;
    const bool do_rope = (seg != 2);
    const float scale  = (seg == 0) ? 0.125f : 1.0f;
    const float* B = ((seg == 0) ? wq : (seg == 1) ? wk : wv) + (size_t)out_col * HID;
    float* out     = (seg == 0) ? g_q : (seg == 1) ? g_k : g_v;

    float acc[2][8][4];
#pragma unroll
    for (int i = 0; i < 2; i++)
#pragma unroll
        for (int j = 0; j < 8; j++)
#pragma unroll
            for (int t = 0; t < 4; t++) acc[i][j][t] = 0.f;

    auto prefetch = [&](int stage, int k0) {
        float* As = sm + stage * (2 * GK_TILE);
        float* Bs = As + GK_TILE;
        uint32_t as_base = (uint32_t)__cvta_generic_to_shared(As);
        uint32_t bs_base = (uint32_t)__cvta_generic_to_shared(Bs);
#pragma unroll
        for (int i = 0; i < 4; i++) {
            int idx = i * 256 + tid;
            int r   = idx >> 3;
            int c4  = idx & 7;
            cp_async16(as_base + (r * GK_PAD + c4 * 4) * 4,
                       &A[(size_t)(brow + r) * HID + k0 + c4 * 4]);
            cp_async16(bs_base + (r * GK_PAD + c4 * 4) * 4,
                       &B[(size_t)r * HID + k0 + c4 * 4]);
        }
        asm volatile("cp.async.commit_group;");
    };

    int stage = 0;
    prefetch(0, 0);

    for (int k0 = 0; k0 < HID; k0 += 32) {
        const bool has_next = (k0 + 32) < HID;
        if (has_next) prefetch(stage ^ 1, k0 + 32);

        if (has_next) asm volatile("cp.async.wait_group 1;");
        else          asm volatile("cp.async.wait_group 0;");
        __syncthreads();

        const float* As = sm + stage * (2 * GK_TILE);
        const float* Bs = As + GK_TILE;

#pragma unroll
        for (int kk = 0; kk < 4; kk++) {
            const int kb = kk * 8;
            uint32_t Af[2][4], Bf[8][2];
#pragma unroll
            for (int mt = 0; mt < 2; mt++) {
                const float* p = &As[(warp_m * 32 + mt * 16 + g) * GK_PAD + kb + cg];
                Af[mt][0] = f2tf32(p[0]);
                Af[mt][1] = f2tf32(p[8 * GK_PAD]);
                Af[mt][2] = f2tf32(p[4]);
                Af[mt][3] = f2tf32(p[8 * GK_PAD + 4]);
            }
#pragma unroll
            for (int nt = 0; nt < 8; nt++) {
                const float* p = &Bs[(warp_n * 64 + nt * 8 + g) * GK_PAD + kb + cg];
                Bf[nt][0] = f2tf32(p[0]);
                Bf[nt][1] = f2tf32(p[4]);
            }
#pragma unroll
            for (int mt = 0; mt < 2; mt++)
#pragma unroll
                for (int nt = 0; nt < 8; nt++)
                    mma_tf32(acc[mt][nt], Af[mt], Bf[nt]);
        }
        __syncthreads();
        stage ^= 1;
    }

    // ---- epilogue: RoPE in registers, then store ----
#pragma unroll
    for (int mt = 0; mt < 2; mt++) {
        const int r0 = brow + warp_m * 32 + mt * 16 + g;   // rows r0, r0+8
        if (do_rope) {
            const float* cb0 = cosb + r0 * HD;
            const float* sb0 = sinb + r0 * HD;
            const float* cb1 = cosb + (r0 + 8) * HD;
            const float* sb1 = sinb + (r0 + 8) * HD;
#pragma unroll
            for (int nt = 0; nt < 4; nt++) {
                const int d = nt * 8 + 2 * cg;             // 0..30 (even)
#pragma unroll
                for (int e = 0; e < 2; e++) {
                    const float cl0 = __ldg(cb0 + d + e);
                    const float sl0 = __ldg(sb0 + d + e);
                    const float ch0 = __ldg(cb0 + d + e + 32);
                    const float sh0 = __ldg(sb0 + d + e + 32);
                    const float cl1 = __ldg(cb1 + d + e);
                    const float sl1 = __ldg(sb1 + d + e);
                    const float ch1 = __ldg(cb1 + d + e + 32);
                    const float sh1 = __ldg(sb1 + d + e + 32);

                    const float x1 = acc[mt][nt][e],     x2 = acc[mt][nt + 4][e];
                    acc[mt][nt][e]     = (x1 * cl0 - x2 * sl0) * scale;
                    acc[mt][nt + 4][e] = (x2 * ch0 + x1 * sh0) * scale;
                    const float y1 = acc[mt][nt][e + 2], y2 = acc[mt][nt + 4][e + 2];
                    acc[mt][nt][e + 2]     = (y1 * cl1 - y2 * sl1) * scale;
                    acc[mt][nt + 4][e + 2] = (y2 * ch1 + y1 * sh1) * scale;
                }
            }
        }
        float* orow0 = out + (size_t)r0 * out_ld + out_col + warp_n * 64;
        float* orow1 = orow0 + (size_t)8 * out_ld;
#pragma unroll
        for (int nt = 0; nt < 8; nt++) {
            const int c = nt * 8 + 2 * cg;
            *reinterpret_cast<float2*>(orow0 + c) = make_float2(acc[mt][nt][0], acc[mt][nt][1]);
            *reinterpret_cast<float2*>(orow1 + c) = make_float2(acc[mt][nt][2], acc[mt][nt][3]);
        }
    }
}

// ============================================================
// Generic C[M,N] = A[M,K] * B[N,K]^T — TF32 (O-proj)
// ============================================================
__global__ __launch_bounds__(256) void gemm_tf32(const float* __restrict__ A,
                                                 const float* __restrict__ B,
                                                 float* __restrict__ C,
                                                 int M, int N, int K) {
    extern __shared__ float sm[];
    const int tid    = threadIdx.x;
    const int lane   = tid & 31;
    const int wid    = tid >> 5;
    const int warp_m = wid >> 2;
    const int warp_n = wid & 3;
    const int g      = lane >> 2;
    const int cg     = lane & 3;
    const int brow   = blockIdx.y * 128;
    const int bcol   = blockIdx.x * 128;

    float acc[4][4][4];
#pragma unroll
    for (int i = 0; i < 4; i++)
#pragma unroll
        for (int j = 0; j < 4; j++)
#pragma unroll
            for (int t = 0; t < 4; t++) acc[i][j][t] = 0.f;

    auto prefetch = [&](int stage, int k0) {
        float* As = sm + stage * (2 * GK_TILE);
        float* Bs = As + GK_TILE;
        uint32_t as_base = (uint32_t)__cvta_generic_to_shared(As);
        uint32_t bs_base = (uint32_t)__cvta_generic_to_shared(Bs);
#pragma unroll
        for (int i = 0; i < 4; i++) {
            int idx = i * 256 + tid;
            int r   = idx >> 3;
            int c4  = idx & 7;
            cp_async16(as_base + (r * GK_PAD + c4 * 4) * 4,
                       &A[(size_t)(brow + r) * K + k0 + c4 * 4]);
            cp_async16(bs_base + (r * GK_PAD + c4 * 4) * 4,
                       &B[(size_t)(bcol + r) * K + k0 + c4 * 4]);
        }
        asm volatile("cp.async.commit_group;");
    };

    int stage = 0;
    prefetch(0, 0);

    for (int k0 = 0; k0 < K; k0 += 32) {
        const bool has_next = (k0 + 32) < K;
        if (has_next) prefetch(stage ^ 1, k0 + 32);

        if (has_next) asm volatile("cp.async.wait_group 1;");
        else          asm volatile("cp.async.wait_group 0;");
        __syncthreads();

        const float* As = sm + stage * (2 * GK_TILE);
        const float* Bs = As + GK_TILE;

#pragma unroll
        for (int kk = 0; kk < 4; kk++) {
            const int kb = kk * 8;
            uint32_t Af[4][4], Bf[4][2];
#pragma unroll
            for (int mt = 0; mt < 4; mt++) {
                const float* p = &As[(warp_m * 64 + mt * 16 + g) * GK_PAD + kb + cg];
                Af[mt][0] = f2tf32(p[0]);
                Af[mt][1] = f2tf32(p[8 * GK_PAD]);
                Af[mt][2] = f2tf32(p[4]);
                Af[mt][3] = f2tf32(p[8 * GK_PAD + 4]);
            }
#pragma unroll
            for (int nt = 0; nt < 4; nt++) {
                const float* p = &Bs[(warp_n * 32 + nt * 8 + g) * GK_PAD + kb + cg];
                Bf[nt][0] = f2tf32(p[0]);
                Bf[nt][1] = f2tf32(p[4]);
            }
#pragma unroll
            for (int mt = 0; mt < 4; mt++)
#pragma unroll
                for (int nt = 0; nt < 4; nt++)
                    mma_tf32(acc[mt][nt], Af[mt], Bf[nt]);
        }
        __syncthreads();
        stage ^= 1;
    }

#pragma unroll
    for (int mt = 0; mt < 4; mt++) {
#pragma unroll
        for (int nt = 0; nt < 4; nt++) {
            int row0 = brow + warp_m * 64 + mt * 16 + g;
            int col  = bcol + warp_n * 32 + nt * 8 + 2 * cg;
            float2 v0 = make_float2(acc[mt][nt][0], acc[mt][nt][1]);
            float2 v1 = make_float2(acc[mt][nt][2], acc[mt][nt][3]);
            *reinterpret_cast<float2*>(&C[(size_t)row0 * N + col])       = v0;
            *reinterpret_cast<float2*>(&C[(size_t)(row0 + 8) * N + col]) = v1;
        }
    }
}

// ============================================================
// TF32 tensor-core causal flash attention (known-good R4 code)
// ============================================================
#define KS_STR 68
#define VS_STR 72
#define FSTAGE (64 * KS_STR + 64 * VS_STR)

__global__ __launch_bounds__(256) void flash_tf32() {
    extern __shared__ float sm[];
    const int tid  = threadIdx.x;
    const int lane = tid & 31;
    const int w    = tid >> 5;
    const int g    = lane >> 2;
    const int cg   = lane & 3;
    const int qt   = gridDim.x - 1 - blockIdx.x;
    const int head = blockIdx.y;
    const int kvh  = head >> 2;
    const int row0 = qt * 128 + w * 16 + g;

    uint32_t qf[8][4];
    {
        const float* q0 = &g_q[(size_t)row0 * DQ + head * HD];
        const float* q1 = q0 + 8 * DQ;
#pragma unroll
        for (int ks = 0; ks < 8; ks++) {
            qf[ks][0] = f2tf32(q0[8 * ks + cg]);
            qf[ks][1] = f2tf32(q1[8 * ks + cg]);
            qf[ks][2] = f2tf32(q0[8 * ks + cg + 4]);
            qf[ks][3] = f2tf32(q1[8 * ks + cg + 4]);
        }
    }

    float oacc[8][4];
#pragma unroll
    for (int nf = 0; nf < 8; nf++)
#pragma unroll
        for (int t = 0; t < 4; t++) oacc[nf][t] = 0.f;
    float m0 = NEG_HUGE, m1 = NEG_HUGE, l0 = 0.f, l1 = 0.f;

    auto prefetch = [&](int kb, int s) {
        float* Ks = sm + s * FSTAGE;
        float* Vs = Ks + 64 * KS_STR;
        uint32_t ka = (uint32_t)__cvta_generic_to_shared(Ks);
        uint32_t va = (uint32_t)__cvta_generic_to_shared(Vs);
#pragma unroll
        for (int t = 0; t < 4; t++) {
            int idx = t * 256 + tid;
            int r   = idx >> 4;
            int c4  = (idx & 15) * 4;
            cp_async16(ka + (r * KS_STR + c4) * 4,
                       &g_k[(size_t)(kb * 64 + r) * DKV + kvh * HD + c4]);
            cp_async16(va + (r * VS_STR + c4) * 4,
                       &g_v[(size_t)(kb * 64 + r) * DKV + kvh * HD + c4]);
        }
        asm volatile("cp.async.commit_group;");
    };

    const int nkb = 2 * qt + 2;
    prefetch(0, 0);

    for (int kb = 0; kb < nkb; kb++) {
        const int s = kb & 1;
        if (kb + 1 < nkb) {
            prefetch(kb + 1, s ^ 1);
            asm volatile("cp.async.wait_group 1;");
        } else {
            asm volatile("cp.async.wait_group 0;");
        }
        __syncthreads();

        const float* Ks = sm + s * FSTAGE;
        const float* Vs = Ks + 64 * KS_STR;

        const bool active = !(w < 4 && kb == 2 * qt + 1);
        if (active) {
            float sacc[8][4];
#pragma unroll
            for (int nf = 0; nf < 8; nf++)
#pragma unroll
                for (int t = 0; t < 4; t++) sacc[nf][t] = 0.f;

#pragma unroll
            for (int ks = 0; ks < 8; ks++) {
#pragma unroll
                for (int nf = 0; nf < 8; nf++) {
                    uint32_t b[2];
                    const float* p = &Ks[(nf * 8 + g) * KS_STR + ks * 8 + cg];
                    b[0] = f2tf32(p[0]);
                    b[1] = f2tf32(p[4]);
                    mma_tf32(sacc[nf], qf[ks], b);
                }
            }

            if (kb >= 2 * qt) {
#pragma unroll
                for (int nf = 0; nf < 8; nf++) {
                    int c = kb * 64 + nf * 8 + 2 * cg;
                    if (c     > row0)     sacc[nf][0] = NEG_HUGE;
                    if (c + 1 > row0)     sacc[nf][1] = NEG_HUGE;
                    if (c     > row0 + 8) sacc[nf][2] = NEG_HUGE;
                    if (c + 1 > row0 + 8) sacc[nf][3] = NEG_HUGE;
                }
            }

            float tm0 = NEG_HUGE, tm1 = NEG_HUGE;
#pragma unroll
            for (int nf = 0; nf < 8; nf++) {
                tm0 = fmaxf(tm0, fmaxf(sacc[nf][0], sacc[nf][1]));
                tm1 = fmaxf(tm1, fmaxf(sacc[nf][2], sacc[nf][3]));
            }
            tm0 = fmaxf(tm0, __shfl_xor_sync(0xffffffff, tm0, 1));
            tm0 = fmaxf(tm0, __shfl_xor_sync(0xffffffff, tm0, 2));
            tm1 = fmaxf(tm1, __shfl_xor_sync(0xffffffff, tm1, 1));
            tm1 = fmaxf(tm1, __shfl_xor_sync(0xffffffff, tm1, 2));

            const float mn0 = fmaxf(m0, tm0);
            const float mn1 = fmaxf(m1, tm1);
            const float sc0 = __expf(m0 - mn0);
            const float sc1 = __expf(m1 - mn1);

            float rs0 = 0.f, rs1 = 0.f;
#pragma unroll
            for (int nf = 0; nf < 8; nf++) {
                sacc[nf][0] = __expf(sacc[nf][0] - mn0);
                sacc[nf][1] = __expf(sacc[nf][1] - mn0);
                sacc[nf][2] = __expf(sacc[nf][2] - mn1);
                sacc[nf][3] = __expf(sacc[nf][3] - mn1);
                rs0 += sacc[nf][0] + sacc[nf][1];
                rs1 += sacc[nf][2] + sacc[nf][3];
            }
            rs0 += __shfl_xor_sync(0xffffffff, rs0, 1);
            rs0 += __shfl_xor_sync(0xffffffff, rs0, 2);
            rs1 += __shfl_xor_sync(0xffffffff, rs1, 1);
            rs1 += __shfl_xor_sync(0xffffffff, rs1, 2);

            l0 = l0 * sc0 + rs0;  m0 = mn0;
            l1 = l1 * sc1 + rs1;  m1 = mn1;
#pragma unroll
            for (int nf = 0; nf < 8; nf++) {
                oacc[nf][0] *= sc0; oacc[nf][1] *= sc0;
                oacc[nf][2] *= sc1; oacc[nf][3] *= sc1;
            }

            const int base = lane & ~3;
            const int s0l  = base + (cg >> 1);
            const int s1l  = s0l + 2;
            const bool odd = (cg & 1);
#pragma unroll
            for (int ks = 0; ks < 8; ks++) {
                const uint32_t c0 = f2tf32(sacc[ks][0]);
                const uint32_t c1 = f2tf32(sacc[ks][1]);
                const uint32_t c2 = f2tf32(sacc[ks][2]);
                const uint32_t c3 = f2tf32(sacc[ks][3]);
                uint32_t a[4];
                {
                    uint32_t t00 = __shfl_sync(0xffffffff, c0, s0l);
                    uint32_t t01 = __shfl_sync(0xffffffff, c1, s0l);
                    uint32_t t10 = __shfl_sync(0xffffffff, c0, s1l);
                    uint32_t t11 = __shfl_sync(0xffffffff, c1, s1l);
                    a[0] = odd ? t01 : t00;
                    a[2] = odd ? t11 : t10;
                    uint32_t u00 = __shfl_sync(0xffffffff, c2, s0l);
                    uint32_t u01 = __shfl_sync(0xffffffff, c3, s0l);
                    uint32_t u10 = __shfl_sync(0xffffffff, c2, s1l);
                    uint32_t u11 = __shfl_sync(0xffffffff, c3, s1l);
                    a[1] = odd ? u01 : u00;
                    a[3] = odd ? u11 : u10;
                }
#pragma unroll
                for (int nf = 0; nf < 8; nf++) {
                    uint32_t b[2];
                    const float* vp = &Vs[(ks * 8 + cg) * VS_STR + nf * 8 + g];
                    b[0] = f2tf32(vp[0]);
                    b[1] = f2tf32(vp[4 * VS_STR]);
                    mma_tf32(oacc[nf], a, b);
                }
            }
        }
        __syncthreads();
    }

    const float inv0 = 1.f / l0;
    const float inv1 = 1.f / l1;
    float* o0 = &g_o[(size_t)row0 * DQ + head * HD];
    float* o1 = o0 + 8 * DQ;
#pragma unroll
    for (int nf = 0; nf < 8; nf++) {
        *reinterpret_cast<float2*>(&o0[nf * 8 + 2 * cg]) =
            make_float2(oacc[nf][0] * inv0, oacc[nf][1] * inv0);
        *reinterpret_cast<float2*>(&o1[nf * 8 + 2 * cg]) =
            make_float2(oacc[nf][2] * inv1, oacc[nf][3] * inv1);
    }
}

// ============================================================
extern "C" void kernel_launch(void* const* d_in, const int* in_sizes, int n_in,
                              void* d_out, int out_size) {
    const float* hs   = (const float*)d_in[0];
    const float* cosb = (const float*)d_in[1];
    const float* sinb = (const float*)d_in[2];
    // d_in[3] = attention_mask (causal) — implemented analytically
    const float* wq   = (const float*)d_in[4];
    const float* wk   = (const float*)d_in[5];
    const float* wv   = (const float*)d_in[6];
    const float* wo   = (const float*)d_in[7];
    float* out = (float*)d_out;

    float* op;
    cudaGetSymbolAddress((void**)&op, g_o);

    const int gemm_smem  = 2 * 2 * GK_TILE * (int)sizeof(float);   // 73728 B
    const int flash_smem = 2 * FSTAGE * (int)sizeof(float);        // 71680 B
    cudaFuncSetAttribute(qkv_gemm,  cudaFuncAttributeMaxDynamicSharedMemorySize, gemm_smem);
    cudaFuncSetAttribute(gemm_tf32, cudaFuncAttributeMaxDynamicSharedMemorySize, gemm_smem);
    cudaFuncSetAttribute(flash_tf32, cudaFuncAttributeMaxDynamicSharedMemorySize, flash_smem);

    // fused QKV projection + RoPE + scale (one chip-filling launch)
    qkv_gemm<<<dim3((DQ + 2 * DKV) / 128, S_LEN / 128), 256, gemm_smem>>>(
        hs, wq, wk, wv, cosb, sinb);

    // TF32 tensor-core causal flash attention
    flash_tf32<<<dim3(S_LEN / 128, NH), 256, flash_smem>>>();

    // output projection
    gemm_tf32<<<dim3(HID / 128, S_LEN / 128), 256, gemm_smem>>>(op, wo, out, S_LEN, HID, HID);
}

// round 8
// speedup vs baseline: 3.8514x; 1.0830x over previous
#include <cuda_runtime.h>
#include <stdint.h>
#include <math.h>

#define S_LEN 2048
#define HID   2048
#define NH    32
#define NKV   8
#define HD    64
#define DQ    (NH * HD)    // 2048
#define DKV   (NKV * HD)   // 512
#define DQKV  (DQ + 2 * DKV)
#define NEG_HUGE (-1e30f)

// -------- scratch (no dynamic allocation allowed) --------
// g_q/g_k/g_v/g_o hold TF32 bit patterns (stored as float)
__device__ float g_q[S_LEN * DQ];       // 16 MB
__device__ float g_k[S_LEN * DKV];      //  4 MB
__device__ float g_v[S_LEN * DKV];      //  4 MB
__device__ float g_o[S_LEN * DQ];       // 16 MB
__device__ float g_hsT[S_LEN * HID];    // 16 MB  tf32(hidden_states)
__device__ float g_wqkvT[DQKV * HID];   // 24 MB  tf32(concat(wq,wk,wv))
__device__ float g_woT[HID * HID];      // 16 MB  tf32(wo)

// ============================================================
// TF32 helpers
// ============================================================
__device__ __forceinline__ uint32_t f2tf32(float x) {
    uint32_t u;
    asm("cvt.rna.tf32.f32 %0, %1;" : "=r"(u) : "f"(x));
    return u;
}

__device__ __forceinline__ void mma_tf32(float c[4], const uint32_t a[4], const uint32_t b[2]) {
    asm volatile(
        "mma.sync.aligned.m16n8k8.row.col.f32.tf32.tf32.f32 "
        "{%0,%1,%2,%3}, {%4,%5,%6,%7}, {%8,%9}, {%0,%1,%2,%3};"
        : "+f"(c[0]), "+f"(c[1]), "+f"(c[2]), "+f"(c[3])
        : "r"(a[0]), "r"(a[1]), "r"(a[2]), "r"(a[3]),
          "r"(b[0]), "r"(b[1]));
}

__device__ __forceinline__ void cp_async16(uint32_t smem_dst, const void* gmem_src) {
    asm volatile("cp.async.cg.shared.global [%0], [%1], 16;" :: "r"(smem_dst), "l"(gmem_src));
}

// ============================================================
// one-time fp32 -> tf32-bits conversion (grid-stride over float4)
// ============================================================
__global__ void cvt_tf32(const float* __restrict__ src, float* __restrict__ dst, int n4) {
    int i = blockIdx.x * blockDim.x + threadIdx.x;
    if (i >= n4) return;
    float4 v = reinterpret_cast<const float4*>(src)[i];
    uint4 u;
    u.x = f2tf32(v.x); u.y = f2tf32(v.y); u.z = f2tf32(v.z); u.w = f2tf32(v.w);
    reinterpret_cast<uint4*>(dst)[i] = u;
}

#define GK_PAD 36
#define GK_TILE (128 * GK_PAD)

// ============================================================
// Fused QKV projection + RoPE + scaling, one launch.
// Inputs pre-converted to tf32 bits -> zero cvt in mainloop.
// Warp layout 4(m) x 2(n): warp tile 32x64 = one full head wide.
// Outputs stored as tf32 bits (flash consumes raw).
// ============================================================
__global__ __launch_bounds__(256) void qkv_gemm(const float* __restrict__ cosb,
                                                const float* __restrict__ sinb) {
    extern __shared__ float sm[];
    const int tid    = threadIdx.x;
    const int lane   = tid & 31;
    const int wid    = tid >> 5;
    const int warp_m = wid & 3;           // 0..3
    const int warp_n = wid >> 2;          // 0..1
    const int g      = lane >> 2;
    const int cg     = lane & 3;
    const int brow   = blockIdx.y * 128;
    const int bcol   = blockIdx.x * 128;

    const int seg = (bcol < DQ) ? 0 : ((bcol < DQ + DKV) ? 1 : 2);
    const int segbase = (seg == 0) ? 0 : ((seg == 1) ? DQ : DQ + DKV);
    const int out_col = bcol - segbase;
    const int out_ld  = (seg == 0) ? DQ : DKV;
    const bool do_rope = (seg != 2);
    const float scale  = (seg == 0) ? 0.125f : 1.0f;
    float* out = (seg == 0) ? g_q : (seg == 1) ? g_k : g_v;

    float acc[2][8][4];
#pragma unroll
    for (int i = 0; i < 2; i++)
#pragma unroll
        for (int j = 0; j < 8; j++)
#pragma unroll
            for (int t = 0; t < 4; t++) acc[i][j][t] = 0.f;

    auto prefetch = [&](int stage, int k0) {
        float* As = sm + stage * (2 * GK_TILE);
        float* Bs = As + GK_TILE;
        uint32_t as_base = (uint32_t)__cvta_generic_to_shared(As);
        uint32_t bs_base = (uint32_t)__cvta_generic_to_shared(Bs);
#pragma unroll
        for (int i = 0; i < 4; i++) {
            int idx = i * 256 + tid;
            int r   = idx >> 3;
            int c4  = idx & 7;
            cp_async16(as_base + (r * GK_PAD + c4 * 4) * 4,
                       &g_hsT[(size_t)(brow + r) * HID + k0 + c4 * 4]);
            cp_async16(bs_base + (r * GK_PAD + c4 * 4) * 4,
                       &g_wqkvT[(size_t)(bcol + r) * HID + k0 + c4 * 4]);
        }
        asm volatile("cp.async.commit_group;");
    };

    int stage = 0;
    prefetch(0, 0);

    for (int k0 = 0; k0 < HID; k0 += 32) {
        const bool has_next = (k0 + 32) < HID;
        if (has_next) prefetch(stage ^ 1, k0 + 32);

        if (has_next) asm volatile("cp.async.wait_group 1;");
        else          asm volatile("cp.async.wait_group 0;");
        __syncthreads();

        const uint32_t* As = reinterpret_cast<const uint32_t*>(sm + stage * (2 * GK_TILE));
        const uint32_t* Bs = As + GK_TILE;

#pragma unroll
        for (int kk = 0; kk < 4; kk++) {
            const int kb = kk * 8;
            uint32_t Af[2][4], Bf[8][2];
#pragma unroll
            for (int mt = 0; mt < 2; mt++) {
                const uint32_t* p = &As[(warp_m * 32 + mt * 16 + g) * GK_PAD + kb + cg];
                Af[mt][0] = p[0];
                Af[mt][1] = p[8 * GK_PAD];
                Af[mt][2] = p[4];
                Af[mt][3] = p[8 * GK_PAD + 4];
            }
#pragma unroll
            for (int nt = 0; nt < 8; nt++) {
                const uint32_t* p = &Bs[(warp_n * 64 + nt * 8 + g) * GK_PAD + kb + cg];
                Bf[nt][0] = p[0];
                Bf[nt][1] = p[4];
            }
#pragma unroll
            for (int mt = 0; mt < 2; mt++)
#pragma unroll
                for (int nt = 0; nt < 8; nt++)
                    mma_tf32(acc[mt][nt], Af[mt], Bf[nt]);
        }
        __syncthreads();
        stage ^= 1;
    }

    // ---- epilogue: RoPE in registers, store tf32 bits ----
#pragma unroll
    for (int mt = 0; mt < 2; mt++) {
        const int r0 = brow + warp_m * 32 + mt * 16 + g;   // rows r0, r0+8
        if (do_rope) {
            const float* cb0 = cosb + r0 * HD;
            const float* sb0 = sinb + r0 * HD;
            const float* cb1 = cosb + (r0 + 8) * HD;
            const float* sb1 = sinb + (r0 + 8) * HD;
#pragma unroll
            for (int nt = 0; nt < 4; nt++) {
                const int d = nt * 8 + 2 * cg;
#pragma unroll
                for (int e = 0; e < 2; e++) {
                    const float cl0 = __ldg(cb0 + d + e);
                    const float sl0 = __ldg(sb0 + d + e);
                    const float ch0 = __ldg(cb0 + d + e + 32);
                    const float sh0 = __ldg(sb0 + d + e + 32);
                    const float cl1 = __ldg(cb1 + d + e);
                    const float sl1 = __ldg(sb1 + d + e);
                    const float ch1 = __ldg(cb1 + d + e + 32);
                    const float sh1 = __ldg(sb1 + d + e + 32);

                    const float x1 = acc[mt][nt][e],     x2 = acc[mt][nt + 4][e];
                    acc[mt][nt][e]     = (x1 * cl0 - x2 * sl0) * scale;
                    acc[mt][nt + 4][e] = (x2 * ch0 + x1 * sh0) * scale;
                    const float y1 = acc[mt][nt][e + 2], y2 = acc[mt][nt + 4][e + 2];
                    acc[mt][nt][e + 2]     = (y1 * cl1 - y2 * sl1) * scale;
                    acc[mt][nt + 4][e + 2] = (y2 * ch1 + y1 * sh1) * scale;
                }
            }
        }
        float* orow0 = out + (size_t)r0 * out_ld + out_col + warp_n * 64;
        float* orow1 = orow0 + (size_t)8 * out_ld;
#pragma unroll
        for (int nt = 0; nt < 8; nt++) {
            const int c = nt * 8 + 2 * cg;
            *reinterpret_cast<float2*>(orow0 + c) =
                make_float2(__uint_as_float(f2tf32(acc[mt][nt][0])),
                            __uint_as_float(f2tf32(acc[mt][nt][1])));
            *reinterpret_cast<float2*>(orow1 + c) =
                make_float2(__uint_as_float(f2tf32(acc[mt][nt][2])),
                            __uint_as_float(f2tf32(acc[mt][nt][3])));
        }
    }
}

// ============================================================
// O-projection: C[M,N] = A[M,K] * B[N,K]^T, A/B pre-tf32 bits.
// C output is fp32 (final result).
// ============================================================
__global__ __launch_bounds__(256) void gemm_tf32(const float* __restrict__ A,
                                                 const float* __restrict__ B,
                                                 float* __restrict__ C,
                                                 int M, int N, int K) {
    extern __shared__ float sm[];
    const int tid    = threadIdx.x;
    const int lane   = tid & 31;
    const int wid    = tid >> 5;
    const int warp_m = wid >> 2;
    const int warp_n = wid & 3;
    const int g      = lane >> 2;
    const int cg     = lane & 3;
    const int brow   = blockIdx.y * 128;
    const int bcol   = blockIdx.x * 128;

    float acc[4][4][4];
#pragma unroll
    for (int i = 0; i < 4; i++)
#pragma unroll
        for (int j = 0; j < 4; j++)
#pragma unroll
            for (int t = 0; t < 4; t++) acc[i][j][t] = 0.f;

    auto prefetch = [&](int stage, int k0) {
        float* As = sm + stage * (2 * GK_TILE);
        float* Bs = As + GK_TILE;
        uint32_t as_base = (uint32_t)__cvta_generic_to_shared(As);
        uint32_t bs_base = (uint32_t)__cvta_generic_to_shared(Bs);
#pragma unroll
        for (int i = 0; i < 4; i++) {
            int idx = i * 256 + tid;
            int r   = idx >> 3;
            int c4  = idx & 7;
            cp_async16(as_base + (r * GK_PAD + c4 * 4) * 4,
                       &A[(size_t)(brow + r) * K + k0 + c4 * 4]);
            cp_async16(bs_base + (r * GK_PAD + c4 * 4) * 4,
                       &B[(size_t)(bcol + r) * K + k0 + c4 * 4]);
        }
        asm volatile("cp.async.commit_group;");
    };

    int stage = 0;
    prefetch(0, 0);

    for (int k0 = 0; k0 < K; k0 += 32) {
        const bool has_next = (k0 + 32) < K;
        if (has_next) prefetch(stage ^ 1, k0 + 32);

        if (has_next) asm volatile("cp.async.wait_group 1;");
        else          asm volatile("cp.async.wait_group 0;");
        __syncthreads();

        const uint32_t* As = reinterpret_cast<const uint32_t*>(sm + stage * (2 * GK_TILE));
        const uint32_t* Bs = As + GK_TILE;

#pragma unroll
        for (int kk = 0; kk < 4; kk++) {
            const int kb = kk * 8;
            uint32_t Af[4][4], Bf[4][2];
#pragma unroll
            for (int mt = 0; mt < 4; mt++) {
                const uint32_t* p = &As[(warp_m * 64 + mt * 16 + g) * GK_PAD + kb + cg];
                Af[mt][0] = p[0];
                Af[mt][1] = p[8 * GK_PAD];
                Af[mt][2] = p[4];
                Af[mt][3] = p[8 * GK_PAD + 4];
            }
#pragma unroll
            for (int nt = 0; nt < 4; nt++) {
                const uint32_t* p = &Bs[(warp_n * 32 + nt * 8 + g) * GK_PAD + kb + cg];
                Bf[nt][0] = p[0];
                Bf[nt][1] = p[4];
            }
#pragma unroll
            for (int mt = 0; mt < 4; mt++)
#pragma unroll
                for (int nt = 0; nt < 4; nt++)
                    mma_tf32(acc[mt][nt], Af[mt], Bf[nt]);
        }
        __syncthreads();
        stage ^= 1;
    }

#pragma unroll
    for (int mt = 0; mt < 4; mt++) {
#pragma unroll
        for (int nt = 0; nt < 4; nt++) {
            int row0 = brow + warp_m * 64 + mt * 16 + g;
            int col  = bcol + warp_n * 32 + nt * 8 + 2 * cg;
            float2 v0 = make_float2(acc[mt][nt][0], acc[mt][nt][1]);
            float2 v1 = make_float2(acc[mt][nt][2], acc[mt][nt][3]);
            *reinterpret_cast<float2*>(&C[(size_t)row0 * N + col])       = v0;
            *reinterpret_cast<float2*>(&C[(size_t)(row0 + 8) * N + col]) = v1;
        }
    }
}

// ============================================================
// TF32 tensor-core causal flash attention.
// Q/K/V arrive as tf32 bits -> no cvt on operand loads.
// ============================================================
#define KS_STR 68
#define VS_STR 72
#define FSTAGE (64 * KS_STR + 64 * VS_STR)

__global__ __launch_bounds__(256) void flash_tf32() {
    extern __shared__ float sm[];
    const int tid  = threadIdx.x;
    const int lane = tid & 31;
    const int w    = tid >> 5;
    const int g    = lane >> 2;
    const int cg   = lane & 3;
    const int qt   = gridDim.x - 1 - blockIdx.x;
    const int head = blockIdx.y;
    const int kvh  = head >> 2;
    const int row0 = qt * 128 + w * 16 + g;

    uint32_t qf[8][4];
    {
        const uint32_t* q0 = reinterpret_cast<const uint32_t*>(&g_q[(size_t)row0 * DQ + head * HD]);
        const uint32_t* q1 = q0 + 8 * DQ;
#pragma unroll
        for (int ks = 0; ks < 8; ks++) {
            qf[ks][0] = q0[8 * ks + cg];
            qf[ks][1] = q1[8 * ks + cg];
            qf[ks][2] = q0[8 * ks + cg + 4];
            qf[ks][3] = q1[8 * ks + cg + 4];
        }
    }

    float oacc[8][4];
#pragma unroll
    for (int nf = 0; nf < 8; nf++)
#pragma unroll
        for (int t = 0; t < 4; t++) oacc[nf][t] = 0.f;
    float m0 = NEG_HUGE, m1 = NEG_HUGE, l0 = 0.f, l1 = 0.f;

    auto prefetch = [&](int kb, int s) {
        float* Ks = sm + s * FSTAGE;
        float* Vs = Ks + 64 * KS_STR;
        uint32_t ka = (uint32_t)__cvta_generic_to_shared(Ks);
        uint32_t va = (uint32_t)__cvta_generic_to_shared(Vs);
#pragma unroll
        for (int t = 0; t < 4; t++) {
            int idx = t * 256 + tid;
            int r   = idx >> 4;
            int c4  = (idx & 15) * 4;
            cp_async16(ka + (r * KS_STR + c4) * 4,
                       &g_k[(size_t)(kb * 64 + r) * DKV + kvh * HD + c4]);
            cp_async16(va + (r * VS_STR + c4) * 4,
                       &g_v[(size_t)(kb * 64 + r) * DKV + kvh * HD + c4]);
        }
        asm volatile("cp.async.commit_group;");
    };

    const int nkb = 2 * qt + 2;
    prefetch(0, 0);

    for (int kb = 0; kb < nkb; kb++) {
        const int s = kb & 1;
        if (kb + 1 < nkb) {
            prefetch(kb + 1, s ^ 1);
            asm volatile("cp.async.wait_group 1;");
        } else {
            asm volatile("cp.async.wait_group 0;");
        }
        __syncthreads();

        const uint32_t* Ks = reinterpret_cast<const uint32_t*>(sm + s * FSTAGE);
        const uint32_t* Vs = Ks + 64 * KS_STR;

        const bool active = !(w < 4 && kb == 2 * qt + 1);
        if (active) {
            float sacc[8][4];
#pragma unroll
            for (int nf = 0; nf < 8; nf++)
#pragma unroll
                for (int t = 0; t < 4; t++) sacc[nf][t] = 0.f;

#pragma unroll
            for (int ks = 0; ks < 8; ks++) {
#pragma unroll
                for (int nf = 0; nf < 8; nf++) {
                    uint32_t b[2];
                    const uint32_t* p = &Ks[(nf * 8 + g) * KS_STR + ks * 8 + cg];
                    b[0] = p[0];
                    b[1] = p[4];
                    mma_tf32(sacc[nf], qf[ks], b);
                }
            }

            if (kb >= 2 * qt) {
#pragma unroll
                for (int nf = 0; nf < 8; nf++) {
                    int c = kb * 64 + nf * 8 + 2 * cg;
                    if (c     > row0)     sacc[nf][0] = NEG_HUGE;
                    if (c + 1 > row0)     sacc[nf][1] = NEG_HUGE;
                    if (c     > row0 + 8) sacc[nf][2] = NEG_HUGE;
                    if (c + 1 > row0 + 8) sacc[nf][3] = NEG_HUGE;
                }
            }

            float tm0 = NEG_HUGE, tm1 = NEG_HUGE;
#pragma unroll
            for (int nf = 0; nf < 8; nf++) {
                tm0 = fmaxf(tm0, fmaxf(sacc[nf][0], sacc[nf][1]));
                tm1 = fmaxf(tm1, fmaxf(sacc[nf][2], sacc[nf][3]));
            }
            tm0 = fmaxf(tm0, __shfl_xor_sync(0xffffffff, tm0, 1));
            tm0 = fmaxf(tm0, __shfl_xor_sync(0xffffffff, tm0, 2));
            tm1 = fmaxf(tm1, __shfl_xor_sync(0xffffffff, tm1, 1));
            tm1 = fmaxf(tm1, __shfl_xor_sync(0xffffffff, tm1, 2));

            const float mn0 = fmaxf(m0, tm0);
            const float mn1 = fmaxf(m1, tm1);
            const float sc0 = __expf(m0 - mn0);
            const float sc1 = __expf(m1 - mn1);

            float rs0 = 0.f, rs1 = 0.f;
#pragma unroll
            for (int nf = 0; nf < 8; nf++) {
                sacc[nf][0] = __expf(sacc[nf][0] - mn0);
                sacc[nf][1] = __expf(sacc[nf][1] - mn0);
                sacc[nf][2] = __expf(sacc[nf][2] - mn1);
                sacc[nf][3] = __expf(sacc[nf][3] - mn1);
                rs0 += sacc[nf][0] + sacc[nf][1];
                rs1 += sacc[nf][2] + sacc[nf][3];
            }
            rs0 += __shfl_xor_sync(0xffffffff, rs0, 1);
            rs0 += __shfl_xor_sync(0xffffffff, rs0, 2);
            rs1 += __shfl_xor_sync(0xffffffff, rs1, 1);
            rs1 += __shfl_xor_sync(0xffffffff, rs1, 2);

            l0 = l0 * sc0 + rs0;  m0 = mn0;
            l1 = l1 * sc1 + rs1;  m1 = mn1;
#pragma unroll
            for (int nf = 0; nf < 8; nf++) {
                oacc[nf][0] *= sc0; oacc[nf][1] *= sc0;
                oacc[nf][2] *= sc1; oacc[nf][3] *= sc1;
            }

            const int base = lane & ~3;
            const int s0l  = base + (cg >> 1);
            const int s1l  = s0l + 2;
            const bool odd = (cg & 1);
#pragma unroll
            for (int ks = 0; ks < 8; ks++) {
                const uint32_t c0 = f2tf32(sacc[ks][0]);
                const uint32_t c1 = f2tf32(sacc[ks][1]);
                const uint32_t c2 = f2tf32(sacc[ks][2]);
                const uint32_t c3 = f2tf32(sacc[ks][3]);
                uint32_t a[4];
                {
                    uint32_t t00 = __shfl_sync(0xffffffff, c0, s0l);
                    uint32_t t01 = __shfl_sync(0xffffffff, c1, s0l);
                    uint32_t t10 = __shfl_sync(0xffffffff, c0, s1l);
                    uint32_t t11 = __shfl_sync(0xffffffff, c1, s1l);
                    a[0] = odd ? t01 : t00;
                    a[2] = odd ? t11 : t10;
                    uint32_t u00 = __shfl_sync(0xffffffff, c2, s0l);
                    uint32_t u01 = __shfl_sync(0xffffffff, c3, s0l);
                    uint32_t u10 = __shfl_sync(0xffffffff, c2, s1l);
                    uint32_t u11 = __shfl_sync(0xffffffff, c3, s1l);
                    a[1] = odd ? u01 : u00;
                    a[3] = odd ? u11 : u10;
                }
#pragma unroll
                for (int nf = 0; nf < 8; nf++) {
                    uint32_t b[2];
                    const uint32_t* vp = &Vs[(ks * 8 + cg) * VS_STR + nf * 8 + g];
                    b[0] = vp[0];
                    b[1] = vp[4 * VS_STR];
                    mma_tf32(oacc[nf], a, b);
                }
            }
        }
        __syncthreads();
    }

    // ---- normalize + store as tf32 bits (O-proj consumes raw) ----
    const float inv0 = 1.f / l0;
    const float inv1 = 1.f / l1;
    float* o0 = &g_o[(size_t)row0 * DQ + head * HD];
    float* o1 = o0 + 8 * DQ;
#pragma unroll
    for (int nf = 0; nf < 8; nf++) {
        *reinterpret_cast<float2*>(&o0[nf * 8 + 2 * cg]) =
            make_float2(__uint_as_float(f2tf32(oacc[nf][0] * inv0)),
                        __uint_as_float(f2tf32(oacc[nf][1] * inv0)));
        *reinterpret_cast<float2*>(&o1[nf * 8 + 2 * cg]) =
            make_float2(__uint_as_float(f2tf32(oacc[nf][2] * inv1)),
                        __uint_as_float(f2tf32(oacc[nf][3] * inv1)));
    }
}

// ============================================================
extern "C" void kernel_launch(void* const* d_in, const int* in_sizes, int n_in,
                              void* d_out, int out_size) {
    const float* hs   = (const float*)d_in[0];
    const float* cosb = (const float*)d_in[1];
    const float* sinb = (const float*)d_in[2];
    // d_in[3] = attention_mask (causal) — implemented analytically
    const float* wq   = (const float*)d_in[4];
    const float* wk   = (const float*)d_in[5];
    const float* wv   = (const float*)d_in[6];
    const float* wo   = (const float*)d_in[7];
    float* out = (float*)d_out;

    float *op, *hsT, *wqkvT, *woT;
    cudaGetSymbolAddress((void**)&op,    g_o);
    cudaGetSymbolAddress((void**)&hsT,   g_hsT);
    cudaGetSymbolAddress((void**)&wqkvT, g_wqkvT);
    cudaGetSymbolAddress((void**)&woT,   g_woT);

    const int gemm_smem  = 2 * 2 * GK_TILE * (int)sizeof(float);   // 73728 B
    const int flash_smem = 2 * FSTAGE * (int)sizeof(float);        // 71680 B
    cudaFuncSetAttribute(qkv_gemm,  cudaFuncAttributeMaxDynamicSharedMemorySize, gemm_smem);
    cudaFuncSetAttribute(gemm_tf32, cudaFuncAttributeMaxDynamicSharedMemorySize, gemm_smem);
    cudaFuncSetAttribute(flash_tf32, cudaFuncAttributeMaxDynamicSharedMemorySize, flash_smem);

    // one-time fp32 -> tf32-bits conversions
    const int CB = 256;
    cvt_tf32<<<(S_LEN * HID / 4 + CB - 1) / CB, CB>>>(hs, hsT, S_LEN * HID / 4);
    cvt_tf32<<<(DQ * HID / 4 + CB - 1) / CB, CB>>>(wq, wqkvT, DQ * HID / 4);
    cvt_tf32<<<(DKV * HID / 4 + CB - 1) / CB, CB>>>(wk, wqkvT + (size_t)DQ * HID, DKV * HID / 4);
    cvt_tf32<<<(DKV * HID / 4 + CB - 1) / CB, CB>>>(wv, wqkvT + (size_t)(DQ + DKV) * HID, DKV * HID / 4);
    cvt_tf32<<<(HID * HID / 4 + CB - 1) / CB, CB>>>(wo, woT, HID * HID / 4);

    // fused QKV projection + RoPE + scale
    qkv_gemm<<<dim3(DQKV / 128, S_LEN / 128), 256, gemm_smem>>>(cosb, sinb);

    // TF32 tensor-core causal flash attention
    flash_tf32<<<dim3(S_LEN / 128, NH), 256, flash_smem>>>();

    // output projection
    gemm_tf32<<<dim3(HID / 128, S_LEN / 128), 256, gemm_smem>>>(op, woT, out, S_LEN, HID, HID);
}